// round 2
// baseline (speedup 1.0000x reference)
#include <cuda_runtime.h>
#include <cuda_bf16.h>
#include <math.h>

// Problem dims (fixed by the dataset)
#define NB    2048          // bags
#define CC    64            // items per bag
#define IND   512
#define HD1   256
#define HD2   256
#define HD3   128
#define DET1  128
#define DET2  64
#define MROWS (NB*CC)       // 131072
#define KDROP 44            // int(64*0.7)
#define TAU   0.95f

// ---------------- scratch (no allocations allowed) ----------------
__device__ float g_H [(size_t)MROWS*HD1];   // 128 MB
__device__ float g_H2[(size_t)MROWS*HD2];   // 128 MB
__device__ float g_H3[(size_t)MROWS*HD3];   //  64 MB
__device__ float g_d1[(size_t)MROWS*DET1];  //  64 MB
__device__ float g_d2[(size_t)MROWS*DET2];  //  32 MB
__device__ float g_scr[MROWS + NB];         // fallback output scratch

// ---------------- tiled fp32 GEMM: C = act(A@B + bias) ----------------
// A: MxK row-major, B: KxN row-major (weights are (fan_in, fan_out)), C: MxN
// ACT: 0=none, 1=relu, 2=sigmoid
template<int BM, int BN, int BK, int TM, int TN, int ACT>
__global__ void __launch_bounds__((BM/TM)*(BN/TN))
gemm_bias_act(const float* __restrict__ A, const float* __restrict__ B,
              const float* __restrict__ bias, float* __restrict__ C,
              int M, int N, int K)
{
    constexpr int TX = BN / TN;
    constexpr int TY = BM / TM;
    constexpr int NT = TX * TY;
    constexpr int AV = BM * BK / 4;   // float4 count for A tile
    constexpr int BV = BK * BN / 4;   // float4 count for B tile

    __shared__ float As[BK][BM];
    __shared__ float Bs[BK][BN + 4];

    const int tid = threadIdx.x;
    const int tx  = tid % TX;
    const int ty  = tid / TX;
    const int m0  = blockIdx.y * BM;
    const int n0  = blockIdx.x * BN;

    float acc[TM][TN];
    #pragma unroll
    for (int i = 0; i < TM; i++)
        #pragma unroll
        for (int j = 0; j < TN; j++) acc[i][j] = 0.0f;

    for (int k0 = 0; k0 < K; k0 += BK) {
        // load A tile (transposed into As[k][m])
        #pragma unroll
        for (int v = tid; v < AV; v += NT) {
            int m  = v / (BK / 4);
            int kq = v % (BK / 4);
            float4 a = *reinterpret_cast<const float4*>(
                &A[(size_t)(m0 + m) * K + k0 + kq * 4]);
            As[kq * 4 + 0][m] = a.x;
            As[kq * 4 + 1][m] = a.y;
            As[kq * 4 + 2][m] = a.z;
            As[kq * 4 + 3][m] = a.w;
        }
        // load B tile
        #pragma unroll
        for (int v = tid; v < BV; v += NT) {
            int kk = v / (BN / 4);
            int nq = v % (BN / 4);
            float4 b = *reinterpret_cast<const float4*>(
                &B[(size_t)(k0 + kk) * N + n0 + nq * 4]);
            *reinterpret_cast<float4*>(&Bs[kk][nq * 4]) = b;
        }
        __syncthreads();

        #pragma unroll
        for (int kk = 0; kk < BK; kk++) {
            float ra[TM], rb[TN];
            #pragma unroll
            for (int i = 0; i < TM; i++) ra[i] = As[kk][ty * TM + i];
            #pragma unroll
            for (int j = 0; j < TN; j++) rb[j] = Bs[kk][tx * TN + j];
            #pragma unroll
            for (int i = 0; i < TM; i++)
                #pragma unroll
                for (int j = 0; j < TN; j++)
                    acc[i][j] = fmaf(ra[i], rb[j], acc[i][j]);
        }
        __syncthreads();
    }

    // epilogue: bias + activation, vectorized stores
    #pragma unroll
    for (int i = 0; i < TM; i++) {
        const int m = m0 + ty * TM + i;
        #pragma unroll
        for (int jq = 0; jq < TN / 4; jq++) {
            const int n = n0 + tx * TN + jq * 4;
            float4 v;
            float* vp = &v.x;
            #pragma unroll
            for (int q = 0; q < 4; q++) {
                float vv = acc[i][jq * 4 + q] + bias[n + q];
                if (ACT == 1) vv = fmaxf(vv, 0.0f);
                else if (ACT == 2) vv = 1.0f / (1.0f + expf(-vv));
                vp[q] = vv;
            }
            *reinterpret_cast<float4*>(&C[(size_t)m * N + n]) = v;
        }
    }
}

// ---------------- per-bag finish ----------------
// computes dd = d2@D3+db3, gumbel softmax over C, rank-dropout, renorm softmax,
// agg = sum_c w_c * H3[n,c,:], out = agg@E + eb
__global__ void __launch_bounds__(128)
finish_kernel(const float* __restrict__ d2v, const float* __restrict__ D3,
              const float* __restrict__ db3, const float* __restrict__ m,
              const float* __restrict__ u,   const float* __restrict__ H3,
              const float* __restrict__ E,   const float* __restrict__ eb,
              float* __restrict__ outw, float* __restrict__ outv)
{
    const int n   = blockIdx.x;
    const int tid = threadIdx.x;   // 128 threads

    __shared__ float s_d2[CC][DET2 + 1];
    __shared__ float s_D3[DET2];
    __shared__ float s_z[CC];
    __shared__ float s_w2[CC];
    __shared__ float s_w[CC];
    __shared__ int   s_keep[CC];
    __shared__ float s_red[128];
    __shared__ float s_mx, s_sum;

    // stage d2 block coalesced
    const float* d2b = d2v + (size_t)n * CC * DET2;
    for (int idx = tid; idx < CC * DET2; idx += 128)
        s_d2[idx >> 6][idx & 63] = d2b[idx];
    if (tid < DET2) s_D3[tid] = D3[tid];
    __syncthreads();

    // dd + gumbel logit
    if (tid < CC) {
        const int c = tid;
        float dd = db3[0];
        #pragma unroll
        for (int j = 0; j < DET2; j++) dd = fmaf(s_d2[c][j], s_D3[j], dd);
        float logit = m[(size_t)n * CC + c] * dd;
        float uu = u[(size_t)n * CC + c];
        float g = -logf(-logf(uu));
        s_z[c] = (logit + g) / TAU;
    }
    __syncthreads();

    // softmax #1 (max-sub, matching jax)
    if (tid == 0) {
        float mx = s_z[0];
        for (int c = 1; c < CC; c++) mx = fmaxf(mx, s_z[c]);
        s_mx = mx;
    }
    __syncthreads();
    if (tid < CC) s_w2[tid] = expf(s_z[tid] - s_mx);
    __syncthreads();
    if (tid == 0) {
        float s = 0.0f;
        for (int c = 0; c < CC; c++) s += s_w2[c];
        s_sum = s;
    }
    __syncthreads();
    if (tid < CC) s_w2[tid] = s_w2[tid] / s_sum;
    __syncthreads();

    // stable-argsort rank: drop the KDROP smallest (ties -> lower index first)
    if (tid < CC) {
        const int c = tid;
        const float v = s_w2[c];
        int rank = 0;
        for (int c2 = 0; c2 < CC; c2++) {
            float v2 = s_w2[c2];
            rank += (v2 < v) || (v2 == v && c2 < c);
        }
        s_keep[c] = (rank >= KDROP);
    }
    __syncthreads();

    // softmax #2 over kept values of w2
    if (tid == 0) {
        float mx = -INFINITY;
        for (int c = 0; c < CC; c++)
            if (s_keep[c]) mx = fmaxf(mx, s_w2[c]);
        s_mx = mx;
    }
    __syncthreads();
    if (tid < CC) s_red[tid] = s_keep[tid] ? expf(s_w2[tid] - s_mx) : 0.0f;
    __syncthreads();
    if (tid == 0) {
        float s = 0.0f;
        for (int c = 0; c < CC; c++) s += s_red[c];
        s_sum = s;
    }
    __syncthreads();
    if (tid < CC) {
        float wv = s_keep[tid] ? s_red[tid] / s_sum : 0.0f;
        s_w[tid] = wv;
        outw[(size_t)n * CC + tid] = wv;
    }
    __syncthreads();

    // agg[d] = sum_c w[c] * H3[n,c,d];  out = sum_d agg[d]*E[d] + eb
    {
        const float* h3b = H3 + (size_t)n * CC * HD3;
        float a = 0.0f;
        #pragma unroll 8
        for (int c = 0; c < CC; c++)
            a = fmaf(s_w[c], h3b[(size_t)c * HD3 + tid], a);
        s_red[tid] = a * E[tid];
    }
    __syncthreads();
    for (int off = 64; off > 0; off >>= 1) {
        if (tid < off) s_red[tid] += s_red[tid + off];
        __syncthreads();
    }
    if (tid == 0) outv[n] = s_red[0] + eb[0];
}

// ---------------- launch ----------------
extern "C" void kernel_launch(void* const* d_in, const int* in_sizes, int n_in,
                              void* d_out, int out_size)
{
    const float* x   = (const float*)d_in[0];
    const float* m   = (const float*)d_in[1];
    const float* u   = (const float*)d_in[2];
    const float* W1  = (const float*)d_in[3];
    const float* b1  = (const float*)d_in[4];
    const float* W2  = (const float*)d_in[5];
    const float* b2  = (const float*)d_in[6];
    const float* W3  = (const float*)d_in[7];
    const float* b3  = (const float*)d_in[8];
    const float* D1  = (const float*)d_in[9];
    const float* db1 = (const float*)d_in[10];
    const float* D2  = (const float*)d_in[11];
    const float* db2 = (const float*)d_in[12];
    const float* D3  = (const float*)d_in[13];
    const float* db3 = (const float*)d_in[14];
    const float* E   = (const float*)d_in[15];
    const float* eb  = (const float*)d_in[16];

    static float *pH = nullptr, *pH2, *pH3, *pd1, *pd2, *pscr;
    if (!pH) {
        cudaGetSymbolAddress((void**)&pH,  g_H);
        cudaGetSymbolAddress((void**)&pH2, g_H2);
        cudaGetSymbolAddress((void**)&pH3, g_H3);
        cudaGetSymbolAddress((void**)&pd1, g_d1);
        cudaGetSymbolAddress((void**)&pd2, g_d2);
        cudaGetSymbolAddress((void**)&pscr, g_scr);
    }

    float* outw = (float*)d_out;
    float* outv;
    if (out_size >= MROWS + NB)      { outv = outw + MROWS; }
    else if (out_size == MROWS)      { outv = pscr; }
    else                             { outv = (float*)d_out; outw = pscr; }

    // layer 1: (131072x512)@(512x256) + relu
    gemm_bias_act<128,128,32,8,8,1><<<dim3(HD1/128, MROWS/128), 256>>>(
        x, W1, b1, pH, MROWS, HD1, IND);
    // layer 2: (131072x256)@(256x256) + relu
    gemm_bias_act<128,128,32,8,8,1><<<dim3(HD2/128, MROWS/128), 256>>>(
        pH, W2, b2, pH2, MROWS, HD2, HD1);
    // layer 3: (131072x256)@(256x128) + relu
    gemm_bias_act<128,128,32,8,8,1><<<dim3(HD3/128, MROWS/128), 256>>>(
        pH2, W3, b3, pH3, MROWS, HD3, HD2);
    // detector 1: (131072x128)@(128x128) + sigmoid
    gemm_bias_act<128,128,32,8,8,2><<<dim3(DET1/128, MROWS/128), 256>>>(
        pH3, D1, db1, pd1, MROWS, DET1, HD3);
    // detector 2: (131072x128)@(128x64) + sigmoid
    gemm_bias_act<128,64,32,8,4,2><<<dim3(DET2/64, MROWS/128), 256>>>(
        pd1, D2, db2, pd2, MROWS, DET2, DET1);
    // per-bag finish
    finish_kernel<<<NB, 128>>>(pd2, D3, db3, m, u, pH3, E, eb, outw, outv);
}

// round 4
// speedup vs baseline: 1.3718x; 1.3718x over previous
#include <cuda_runtime.h>
#include <cuda_bf16.h>
#include <math.h>
#include <stdint.h>

// Problem dims (fixed by the dataset)
#define NB    2048
#define CC    64
#define IND   512
#define HD1   256
#define HD2   256
#define HD3   128
#define DET1  128
#define DET2  64
#define MROWS (NB*CC)       // 131072
#define KDROP 44
#define TAU   0.95f
#define PAD   20            // smem row pad (floats): conflict-free frag loads

// ---------------- scratch (no allocations allowed) ----------------
__device__ float g_H [(size_t)MROWS*HD1];
__device__ float g_H2[(size_t)MROWS*HD2];
__device__ float g_H3[(size_t)MROWS*HD3];
__device__ float g_d1[(size_t)MROWS*DET1];
__device__ float g_d2[(size_t)MROWS*DET2];
__device__ float g_scr[MROWS + NB];
// transposed + tf32-decomposed weights (N-major, N x K each)
__device__ float g_wth[262144];
__device__ float g_wtl[262144];
#define OFF_W1 0
#define OFF_W2 131072
#define OFF_W3 196608
#define OFF_D1 229376
#define OFF_D2 245760

// ---------------- PTX helpers (portable sm_80+ only; NO tcgen05) ----------------
__device__ __forceinline__ uint32_t smem_u32(const void* p) {
    uint32_t a;
    asm("{ .reg .u64 t; cvta.to.shared.u64 t, %1; cvt.u32.u64 %0, t; }" : "=r"(a) : "l"(p));
    return a;
}
__device__ __forceinline__ float to_tf32(float x) {
    uint32_t r;
    asm("cvt.rna.tf32.f32 %0, %1;" : "=r"(r) : "f"(x));
    return __uint_as_float(r);
}
__device__ __forceinline__ void cp16(uint32_t dst, const void* src) {
    asm volatile("cp.async.cg.shared.global [%0], [%1], 16;" :: "r"(dst), "l"(src) : "memory");
}
__device__ __forceinline__ void cp_commit() {
    asm volatile("cp.async.commit_group;" ::: "memory");
}
// d += a(tf32 16x8) * b(tf32 8x8)
__device__ __forceinline__ void mma_tf32(float* c, const float* a_, const float* b_) {
    const uint32_t* a = reinterpret_cast<const uint32_t*>(a_);
    const uint32_t* b = reinterpret_cast<const uint32_t*>(b_);
    asm volatile(
        "mma.sync.aligned.m16n8k8.row.col.f32.tf32.tf32.f32 "
        "{%0,%1,%2,%3}, {%4,%5,%6,%7}, {%8,%9}, {%0,%1,%2,%3};"
        : "+f"(c[0]), "+f"(c[1]), "+f"(c[2]), "+f"(c[3])
        : "r"(a[0]), "r"(a[1]), "r"(a[2]), "r"(a[3]), "r"(b[0]), "r"(b[1]));
}

// ---------------- weight prep: transpose (K,N)->(N,K) + tf32 hi/lo split ----------------
__global__ void prep_weights(const float* __restrict__ W, float* __restrict__ th,
                             float* __restrict__ tl, int K, int N)
{
    int i = blockIdx.x * 256 + threadIdx.x;
    if (i >= K * N) return;
    int k = i / N, n = i % N;
    float x = W[i];
    float h = to_tf32(x);
    float l = to_tf32(x - h);
    th[(size_t)n * K + k] = h;
    tl[(size_t)n * K + k] = l;
}

// ---------------- mma.sync tf32 3x GEMM: C = act(A@B + bias) ----------------
// A: MxK row-major fp32 (split to hi/lo on the fly).
// Bgh/Bgl: NxK row-major (pre-transposed + decomposed weights).
// CTA: 128(M) x BN(N), 4 warps (2x2), warp tile 64 x BN/2, BK=16 (2 k-steps).
// ACT: 1=relu, 2=sigmoid
template<int BN, int ACT>
__global__ void __launch_bounds__(128, 2)
mma_gemm(const float* __restrict__ A, const float* __restrict__ Bgh,
         const float* __restrict__ Bgl, const float* __restrict__ bias,
         float* __restrict__ C, int K, int Ntot)
{
    constexpr int NT   = BN / 16;          // n8 tiles per warp (WN = BN/2)
    constexpr int ABUF = 128 * PAD;        // floats per A region
    constexpr int BBUF = BN * PAD;
    constexpr int BUF  = 2 * ABUF + 2 * BBUF;
    extern __shared__ float sm[];

    const int tid  = threadIdx.x;
    const int wid  = tid >> 5, lane = tid & 31;
    const int wm   = wid >> 1, wn = wid & 1;
    const int g    = lane >> 2, tig = lane & 3;
    const int m0   = blockIdx.y * 128;
    const int n0   = blockIdx.x * BN;

    float acc[4][NT][4];
    #pragma unroll
    for (int i = 0; i < 4; i++)
        #pragma unroll
        for (int j = 0; j < NT; j++)
            #pragma unroll
            for (int q = 0; q < 4; q++) acc[i][j][q] = 0.0f;

    const int NC  = K >> 4;
    const int am  = tid >> 2;      // A load: row offset (within 32-row group)
    const int akq = tid & 3;       // A load: 16B column group

    float4 rA[4];

    // ---------------- prologue: LDG A chunk 0, cp.async B chunk 0 -> buf 0 ----
    #pragma unroll
    for (int it = 0; it < 4; ++it)
        rA[it] = *reinterpret_cast<const float4*>(
            A + (size_t)(m0 + am + it * 32) * K + akq * 4);
    {
        uint32_t dh = smem_u32(sm + 2 * ABUF);
        uint32_t dl = dh + BBUF * 4;
        #pragma unroll
        for (int it = 0; it < BN / 32; ++it) {
            int idx = tid + it * 128;
            int n = idx >> 2, kq = idx & 3;
            size_t so = (size_t)(n0 + n) * K + kq * 4;
            uint32_t doff = (uint32_t)(n * PAD + kq * 4) * 4;
            cp16(dh + doff, Bgh + so);
            cp16(dl + doff, Bgl + so);
        }
        cp_commit();
    }

    for (int c = 0; c < NC; ++c) {
        const int b = c & 1;
        float* base = sm + b * BUF;
        // issue cp.async for chunk c+1 into the other buffer
        if (c + 1 < NC) {
            float* nb = sm + (b ^ 1) * BUF;
            uint32_t dh = smem_u32(nb + 2 * ABUF);
            uint32_t dl = dh + BBUF * 4;
            const int k1 = (c + 1) << 4;
            #pragma unroll
            for (int it = 0; it < BN / 32; ++it) {
                int idx = tid + it * 128;
                int n = idx >> 2, kq = idx & 3;
                size_t so = (size_t)(n0 + n) * K + k1 + kq * 4;
                uint32_t doff = (uint32_t)(n * PAD + kq * 4) * 4;
                cp16(dh + doff, Bgh + so);
                cp16(dl + doff, Bgl + so);
            }
            cp_commit();
        }
        // STS A chunk c (convert to hi/lo)
        {
            float* Ah = base;
            float* Al = base + ABUF;
            #pragma unroll
            for (int it = 0; it < 4; ++it) {
                int m = am + it * 32;
                float4 h, l;
                h.x = to_tf32(rA[it].x); l.x = to_tf32(rA[it].x - h.x);
                h.y = to_tf32(rA[it].y); l.y = to_tf32(rA[it].y - h.y);
                h.z = to_tf32(rA[it].z); l.z = to_tf32(rA[it].z - h.z);
                h.w = to_tf32(rA[it].w); l.w = to_tf32(rA[it].w - h.w);
                *reinterpret_cast<float4*>(Ah + m * PAD + akq * 4) = h;
                *reinterpret_cast<float4*>(Al + m * PAD + akq * 4) = l;
            }
        }
        // LDG A chunk c+1
        if (c + 1 < NC) {
            const float* An = A + (size_t)m0 * K + ((c + 1) << 4);
            #pragma unroll
            for (int it = 0; it < 4; ++it)
                rA[it] = *reinterpret_cast<const float4*>(
                    An + (size_t)(am + it * 32) * K + akq * 4);
        }
        if (c + 1 < NC) asm volatile("cp.async.wait_group 1;" ::: "memory");
        else            asm volatile("cp.async.wait_group 0;" ::: "memory");
        __syncthreads();

        // ---- compute: 2 k-steps x 3 terms x (4 x NT) mma ----
        const float* sAh = base;
        const float* sAl = base + ABUF;
        const float* sBh = base + 2 * ABUF;
        const float* sBl = base + 2 * ABUF + BBUF;
        #pragma unroll
        for (int ks = 0; ks < 2; ++ks) {
            const int kb = ks * 8 + tig;
            float ah[4][4], al[4][4], bh[NT][2], bl[NT][2];
            #pragma unroll
            for (int mt = 0; mt < 4; ++mt) {
                const int mr = wm * 64 + mt * 16 + g;
                ah[mt][0] = sAh[mr * PAD + kb];
                ah[mt][1] = sAh[(mr + 8) * PAD + kb];
                ah[mt][2] = sAh[mr * PAD + kb + 4];
                ah[mt][3] = sAh[(mr + 8) * PAD + kb + 4];
                al[mt][0] = sAl[mr * PAD + kb];
                al[mt][1] = sAl[(mr + 8) * PAD + kb];
                al[mt][2] = sAl[mr * PAD + kb + 4];
                al[mt][3] = sAl[(mr + 8) * PAD + kb + 4];
            }
            #pragma unroll
            for (int nt = 0; nt < NT; ++nt) {
                const int nc = wn * (NT * 8) + nt * 8 + g;
                bh[nt][0] = sBh[nc * PAD + kb];
                bh[nt][1] = sBh[nc * PAD + kb + 4];
                bl[nt][0] = sBl[nc * PAD + kb];
                bl[nt][1] = sBl[nc * PAD + kb + 4];
            }
            #pragma unroll
            for (int mt = 0; mt < 4; ++mt)
                #pragma unroll
                for (int nt = 0; nt < NT; ++nt) {
                    mma_tf32(acc[mt][nt], ah[mt], bh[nt]);
                    mma_tf32(acc[mt][nt], ah[mt], bl[nt]);
                    mma_tf32(acc[mt][nt], al[mt], bh[nt]);
                }
        }
        __syncthreads();
    }

    // ---------------- epilogue: bias + act + store ----------------
    #pragma unroll
    for (int mt = 0; mt < 4; ++mt) {
        const int row = m0 + wm * 64 + mt * 16 + g;
        #pragma unroll
        for (int nt = 0; nt < NT; ++nt) {
            const int col = n0 + wn * (NT * 8) + nt * 8 + tig * 2;
            const float b0 = bias[col], b1 = bias[col + 1];
            float v0 = acc[mt][nt][0] + b0;
            float v1 = acc[mt][nt][1] + b1;
            float v2 = acc[mt][nt][2] + b0;
            float v3 = acc[mt][nt][3] + b1;
            if (ACT == 1) {
                v0 = fmaxf(v0, 0.0f); v1 = fmaxf(v1, 0.0f);
                v2 = fmaxf(v2, 0.0f); v3 = fmaxf(v3, 0.0f);
            } else if (ACT == 2) {
                v0 = 1.0f / (1.0f + expf(-v0)); v1 = 1.0f / (1.0f + expf(-v1));
                v2 = 1.0f / (1.0f + expf(-v2)); v3 = 1.0f / (1.0f + expf(-v3));
            }
            float2 p0 = make_float2(v0, v1);
            float2 p1 = make_float2(v2, v3);
            *reinterpret_cast<float2*>(C + (size_t)row * Ntot + col) = p0;
            *reinterpret_cast<float2*>(C + (size_t)(row + 8) * Ntot + col) = p1;
        }
    }
}

// ---------------- per-bag finish (unchanged, passed R2) ----------------
__global__ void __launch_bounds__(128)
finish_kernel(const float* __restrict__ d2v, const float* __restrict__ D3,
              const float* __restrict__ db3, const float* __restrict__ m,
              const float* __restrict__ u,   const float* __restrict__ H3,
              const float* __restrict__ E,   const float* __restrict__ eb,
              float* __restrict__ outw, float* __restrict__ outv)
{
    const int n   = blockIdx.x;
    const int tid = threadIdx.x;

    __shared__ float s_d2[CC][DET2 + 1];
    __shared__ float s_D3[DET2];
    __shared__ float s_z[CC];
    __shared__ float s_w2[CC];
    __shared__ float s_w[CC];
    __shared__ int   s_keep[CC];
    __shared__ float s_red[128];
    __shared__ float s_mx, s_sum;

    const float* d2b = d2v + (size_t)n * CC * DET2;
    for (int idx = tid; idx < CC * DET2; idx += 128)
        s_d2[idx >> 6][idx & 63] = d2b[idx];
    if (tid < DET2) s_D3[tid] = D3[tid];
    __syncthreads();

    if (tid < CC) {
        const int c = tid;
        float dd = db3[0];
        #pragma unroll
        for (int j = 0; j < DET2; j++) dd = fmaf(s_d2[c][j], s_D3[j], dd);
        float logit = m[(size_t)n * CC + c] * dd;
        float uu = u[(size_t)n * CC + c];
        float gn = -logf(-logf(uu));
        s_z[c] = (logit + gn) / TAU;
    }
    __syncthreads();

    if (tid == 0) {
        float mx = s_z[0];
        for (int c = 1; c < CC; c++) mx = fmaxf(mx, s_z[c]);
        s_mx = mx;
    }
    __syncthreads();
    if (tid < CC) s_w2[tid] = expf(s_z[tid] - s_mx);
    __syncthreads();
    if (tid == 0) {
        float s = 0.0f;
        for (int c = 0; c < CC; c++) s += s_w2[c];
        s_sum = s;
    }
    __syncthreads();
    if (tid < CC) s_w2[tid] = s_w2[tid] / s_sum;
    __syncthreads();

    if (tid < CC) {
        const int c = tid;
        const float v = s_w2[c];
        int rank = 0;
        for (int c2 = 0; c2 < CC; c2++) {
            float v2 = s_w2[c2];
            rank += (v2 < v) || (v2 == v && c2 < c);
        }
        s_keep[c] = (rank >= KDROP);
    }
    __syncthreads();

    if (tid == 0) {
        float mx = -INFINITY;
        for (int c = 0; c < CC; c++)
            if (s_keep[c]) mx = fmaxf(mx, s_w2[c]);
        s_mx = mx;
    }
    __syncthreads();
    if (tid < CC) s_red[tid] = s_keep[tid] ? expf(s_w2[tid] - s_mx) : 0.0f;
    __syncthreads();
    if (tid == 0) {
        float s = 0.0f;
        for (int c = 0; c < CC; c++) s += s_red[c];
        s_sum = s;
    }
    __syncthreads();
    if (tid < CC) {
        float wv = s_keep[tid] ? s_red[tid] / s_sum : 0.0f;
        s_w[tid] = wv;
        outw[(size_t)n * CC + tid] = wv;
    }
    __syncthreads();

    {
        const float* h3b = H3 + (size_t)n * CC * HD3;
        float a = 0.0f;
        #pragma unroll 8
        for (int c = 0; c < CC; c++)
            a = fmaf(s_w[c], h3b[(size_t)c * HD3 + tid], a);
        s_red[tid] = a * E[tid];
    }
    __syncthreads();
    for (int off = 64; off > 0; off >>= 1) {
        if (tid < off) s_red[tid] += s_red[tid + off];
        __syncthreads();
    }
    if (tid == 0) outv[n] = s_red[0] + eb[0];
}

// ---------------- launch ----------------
static inline int smem_bytes_for(int BN) {
    return 2 * (2 * 128 * PAD + 2 * BN * PAD) * 4;
}

extern "C" void kernel_launch(void* const* d_in, const int* in_sizes, int n_in,
                              void* d_out, int out_size)
{
    const float* x   = (const float*)d_in[0];
    const float* m   = (const float*)d_in[1];
    const float* u   = (const float*)d_in[2];
    const float* W1  = (const float*)d_in[3];
    const float* b1  = (const float*)d_in[4];
    const float* W2  = (const float*)d_in[5];
    const float* b2  = (const float*)d_in[6];
    const float* W3  = (const float*)d_in[7];
    const float* b3  = (const float*)d_in[8];
    const float* D1  = (const float*)d_in[9];
    const float* db1 = (const float*)d_in[10];
    const float* D2  = (const float*)d_in[11];
    const float* db2 = (const float*)d_in[12];
    const float* D3  = (const float*)d_in[13];
    const float* db3 = (const float*)d_in[14];
    const float* E   = (const float*)d_in[15];
    const float* eb  = (const float*)d_in[16];

    static float *pH = nullptr, *pH2, *pH3, *pd1, *pd2, *pscr, *pwth, *pwtl;
    if (!pH) {
        cudaGetSymbolAddress((void**)&pH,   g_H);
        cudaGetSymbolAddress((void**)&pH2,  g_H2);
        cudaGetSymbolAddress((void**)&pH3,  g_H3);
        cudaGetSymbolAddress((void**)&pd1,  g_d1);
        cudaGetSymbolAddress((void**)&pd2,  g_d2);
        cudaGetSymbolAddress((void**)&pscr, g_scr);
        cudaGetSymbolAddress((void**)&pwth, g_wth);
        cudaGetSymbolAddress((void**)&pwtl, g_wtl);
        cudaFuncSetAttribute(mma_gemm<128,1>, cudaFuncAttributeMaxDynamicSharedMemorySize, smem_bytes_for(128));
        cudaFuncSetAttribute(mma_gemm<128,2>, cudaFuncAttributeMaxDynamicSharedMemorySize, smem_bytes_for(128));
        cudaFuncSetAttribute(mma_gemm<64,2>,  cudaFuncAttributeMaxDynamicSharedMemorySize, smem_bytes_for(64));
    }

    float* outw = (float*)d_out;
    float* outv;
    if (out_size >= MROWS + NB)      { outv = outw + MROWS; }
    else if (out_size == MROWS)      { outv = pscr; }
    else                             { outv = (float*)d_out; outw = pscr; }

    // weight prep: transpose + tf32 decompose
    prep_weights<<<(IND*HD1 + 255)/256, 256>>>(W1, pwth + OFF_W1, pwtl + OFF_W1, IND,  HD1);
    prep_weights<<<(HD1*HD2 + 255)/256, 256>>>(W2, pwth + OFF_W2, pwtl + OFF_W2, HD1,  HD2);
    prep_weights<<<(HD2*HD3 + 255)/256, 256>>>(W3, pwth + OFF_W3, pwtl + OFF_W3, HD2,  HD3);
    prep_weights<<<(HD3*DET1 + 255)/256, 256>>>(D1, pwth + OFF_D1, pwtl + OFF_D1, HD3,  DET1);
    prep_weights<<<(DET1*DET2 + 255)/256, 256>>>(D2, pwth + OFF_D2, pwtl + OFF_D2, DET1, DET2);

    const int gy = MROWS / 128;   // 1024
    // layer 1: K=512, N=256
    mma_gemm<128,1><<<dim3(2, gy), 128, smem_bytes_for(128)>>>(
        x,   pwth + OFF_W1, pwtl + OFF_W1, b1,  pH,  IND,  HD1);
    // layer 2: K=256, N=256
    mma_gemm<128,1><<<dim3(2, gy), 128, smem_bytes_for(128)>>>(
        pH,  pwth + OFF_W2, pwtl + OFF_W2, b2,  pH2, HD1,  HD2);
    // layer 3: K=256, N=128
    mma_gemm<128,1><<<dim3(1, gy), 128, smem_bytes_for(128)>>>(
        pH2, pwth + OFF_W3, pwtl + OFF_W3, b3,  pH3, HD2,  HD3);
    // detector 1: K=128, N=128, sigmoid
    mma_gemm<128,2><<<dim3(1, gy), 128, smem_bytes_for(128)>>>(
        pH3, pwth + OFF_D1, pwtl + OFF_D1, db1, pd1, HD3,  DET1);
    // detector 2: K=128, N=64, sigmoid
    mma_gemm<64,2><<<dim3(1, gy), 128, smem_bytes_for(64)>>>(
        pd1, pwth + OFF_D2, pwtl + OFF_D2, db2, pd2, DET1, DET2);

    finish_kernel<<<NB, 128>>>(pd2, D3, db3, m, u, pH3, E, eb, outw, outv);
}

// round 5
// speedup vs baseline: 2.3627x; 1.7224x over previous
#include <cuda_runtime.h>
#include <cuda_fp16.h>
#include <math.h>
#include <stdint.h>

// Problem dims (fixed by the dataset)
#define NB    2048
#define CC    64
#define IND   512
#define HD1   256
#define HD2   256
#define HD3   128
#define DET1  128
#define DET2  64
#define MROWS (NB*CC)       // 131072
#define KDROP 44
#define TAU   0.95f

// smem row stride: 40 halves = 80 bytes -> ldmatrix phases conflict-free
#define RS    40

// ---------------- scratch (no allocations allowed) ----------------
__device__ float g_H [(size_t)MROWS*HD1];
__device__ float g_H2[(size_t)MROWS*HD2];
__device__ float g_H3[(size_t)MROWS*HD3];
__device__ float g_d1[(size_t)MROWS*DET1];
__device__ float g_d2[(size_t)MROWS*DET2];
__device__ float g_scr[MROWS + NB];
// transposed + fp16 hi/lo decomposed weights (N-major, N x K each)
__device__ __half g_wh[262144];
__device__ __half g_wl[262144];
#define OFF_W1 0
#define OFF_W2 131072
#define OFF_W3 196608
#define OFF_D1 229376
#define OFF_D2 245760

// ---------------- PTX helpers (sm_80-portable; NO tcgen05) ----------------
__device__ __forceinline__ uint32_t smem_u32(const void* p) {
    uint32_t a;
    asm("{ .reg .u64 t; cvta.to.shared.u64 t, %1; cvt.u32.u64 %0, t; }" : "=r"(a) : "l"(p));
    return a;
}
__device__ __forceinline__ void cp16(uint32_t dst, const void* src) {
    asm volatile("cp.async.cg.shared.global [%0], [%1], 16;" :: "r"(dst), "l"(src) : "memory");
}
__device__ __forceinline__ void cp_commit() {
    asm volatile("cp.async.commit_group;" ::: "memory");
}
__device__ __forceinline__ void ldm_x4(uint32_t* r, uint32_t addr) {
    asm volatile("ldmatrix.sync.aligned.m8n8.x4.shared.b16 {%0,%1,%2,%3}, [%4];"
        : "=r"(r[0]), "=r"(r[1]), "=r"(r[2]), "=r"(r[3]) : "r"(addr));
}
// c += A(16x16 f16) * B(16x8 f16), f32 accum
__device__ __forceinline__ void mma_f16(float* c, const uint32_t* a, const uint32_t* b) {
    asm volatile(
        "mma.sync.aligned.m16n8k16.row.col.f32.f16.f16.f32 "
        "{%0,%1,%2,%3}, {%4,%5,%6,%7}, {%8,%9}, {%0,%1,%2,%3};"
        : "+f"(c[0]), "+f"(c[1]), "+f"(c[2]), "+f"(c[3])
        : "r"(a[0]), "r"(a[1]), "r"(a[2]), "r"(a[3]), "r"(b[0]), "r"(b[1]));
}
__device__ __forceinline__ uint32_t pack2(__half a, __half b) {
    __half2 h2 = __halves2half2(a, b);
    return *reinterpret_cast<uint32_t*>(&h2);
}

// ---------------- weight prep: transpose (K,N)->(N,K) + fp16 hi/lo split ------
__global__ void prep_weights(const float* __restrict__ W, __half* __restrict__ th,
                             __half* __restrict__ tl, int K, int N)
{
    int i = blockIdx.x * 256 + threadIdx.x;
    if (i >= K * N) return;
    int k = i / N, n = i % N;
    float x = W[i];
    __half h = __float2half_rn(x);
    __half l = __float2half_rn(x - __half2float(h));
    th[(size_t)n * K + k] = h;
    tl[(size_t)n * K + k] = l;
}

// ---------------- fp16 3x HMMA GEMM: C = act(A@B + bias) ----------------
// A: MxK row-major fp32 (split to fp16 hi/lo on the fly).
// Bgh/Bgl: NxK row-major fp16 (pre-transposed + decomposed weights).
// CTA: 128(M) x BN(N), 4 warps (2x2), warp tile 64 x BN/2, BK=32 (2 k16-steps).
// ACT: 1=relu, 2=sigmoid
template<int BN, int ACT>
__global__ void __launch_bounds__(128, 2)
mma_gemm_h(const float* __restrict__ A, const __half* __restrict__ Bgh,
           const __half* __restrict__ Bgl, const float* __restrict__ bias,
           float* __restrict__ C, int K, int Ntot)
{
    constexpr int NT   = BN / 16;          // n8 tiles per warp
    constexpr int NP   = NT / 2;           // ldmatrix x4 tile-pairs
    constexpr int AB   = 128 * RS * 2;     // bytes per A region (hi or lo)
    constexpr int BB   = BN * RS * 2;      // bytes per B region
    constexpr int BUFB = 2 * AB + 2 * BB;  // bytes per pipeline buffer
    extern __shared__ char smem[];
    const uint32_t sb = smem_u32(smem);

    const int tid  = threadIdx.x;
    const int wid  = tid >> 5, lane = tid & 31;
    const int wm   = wid >> 1, wn = wid & 1;
    const int g    = lane >> 2, tig = lane & 3;
    const int m0   = blockIdx.y * 128;
    const int n0   = blockIdx.x * BN;

    // ldmatrix per-thread offsets (in bytes)
    const int arow  = lane & 15;
    const int akoff = (lane >> 4) << 3;                 // 0 or 8 halves
    const uint32_t aoff = (uint32_t)(arow * RS + akoff) * 2;
    const int brow  = (lane & 7) + ((lane >> 4) & 1) * 8;
    const int bkoff = ((lane >> 3) & 1) << 3;
    const uint32_t boff = (uint32_t)(brow * RS + bkoff) * 2;

    float acc[4][NT][4];
    #pragma unroll
    for (int i = 0; i < 4; i++)
        #pragma unroll
        for (int j = 0; j < NT; j++)
            #pragma unroll
            for (int q = 0; q < 4; q++) acc[i][j][q] = 0.0f;

    const int NC  = K >> 5;                // K/32 chunks
    const int ar  = tid >> 3;              // A stage: row within 16-row group
    const int akq = tid & 7;               // A stage: 16B col group (4 floats)

    float4 rA[8];

    // ---- prologue: LDG A chunk0, cp.async B chunk0 -> buf0 ----
    #pragma unroll
    for (int it = 0; it < 8; ++it)
        rA[it] = *reinterpret_cast<const float4*>(
            A + (size_t)(m0 + ar + it * 16) * K + akq * 4);
    {
        uint32_t dh = sb + 2 * AB;
        uint32_t dl = dh + BB;
        #pragma unroll
        for (int it = 0; it < BN / 32; ++it) {
            int idx = tid + it * 128;
            int n = idx >> 2, kc = idx & 3;
            size_t so = (size_t)(n0 + n) * K + kc * 8;
            uint32_t doff = (uint32_t)(n * RS + kc * 8) * 2;
            cp16(dh + doff, Bgh + so);
            cp16(dl + doff, Bgl + so);
        }
        cp_commit();
    }

    for (int c = 0; c < NC; ++c) {
        const int b = c & 1;
        const uint32_t base = sb + b * BUFB;
        // cp.async B for chunk c+1 into other buffer
        if (c + 1 < NC) {
            uint32_t dh = sb + (b ^ 1) * BUFB + 2 * AB;
            uint32_t dl = dh + BB;
            const int k1 = (c + 1) << 5;
            #pragma unroll
            for (int it = 0; it < BN / 32; ++it) {
                int idx = tid + it * 128;
                int n = idx >> 2, kc = idx & 3;
                size_t so = (size_t)(n0 + n) * K + k1 + kc * 8;
                uint32_t doff = (uint32_t)(n * RS + kc * 8) * 2;
                cp16(dh + doff, Bgh + so);
                cp16(dl + doff, Bgl + so);
            }
            cp_commit();
        }
        // STS A chunk c (fp32 -> fp16 hi/lo)
        {
            __half* Ah = reinterpret_cast<__half*>(smem + b * BUFB);
            __half* Al = reinterpret_cast<__half*>(smem + b * BUFB + AB);
            #pragma unroll
            for (int it = 0; it < 8; ++it) {
                const int row = ar + it * 16;
                const float4 a = rA[it];
                __half hx = __float2half_rn(a.x), hy = __float2half_rn(a.y);
                __half hz = __float2half_rn(a.z), hw = __float2half_rn(a.w);
                __half lx = __float2half_rn(a.x - __half2float(hx));
                __half ly = __float2half_rn(a.y - __half2float(hy));
                __half lz = __float2half_rn(a.z - __half2float(hz));
                __half lw = __float2half_rn(a.w - __half2float(hw));
                uint2 ph = make_uint2(pack2(hx, hy), pack2(hz, hw));
                uint2 pl = make_uint2(pack2(lx, ly), pack2(lz, lw));
                *reinterpret_cast<uint2*>(Ah + row * RS + akq * 4) = ph;
                *reinterpret_cast<uint2*>(Al + row * RS + akq * 4) = pl;
            }
        }
        // LDG A chunk c+1
        if (c + 1 < NC) {
            const float* An = A + (size_t)m0 * K + ((c + 1) << 5);
            #pragma unroll
            for (int it = 0; it < 8; ++it)
                rA[it] = *reinterpret_cast<const float4*>(
                    An + (size_t)(ar + it * 16) * K + akq * 4);
        }
        if (c + 1 < NC) asm volatile("cp.async.wait_group 1;" ::: "memory");
        else            asm volatile("cp.async.wait_group 0;" ::: "memory");
        __syncthreads();

        // ---- compute: 2 k16-steps x 3 terms ----
        const uint32_t sAh = base;
        const uint32_t sAl = base + AB;
        const uint32_t sBh = base + 2 * AB;
        const uint32_t sBl = sBh + BB;
        #pragma unroll
        for (int ks = 0; ks < 2; ++ks) {
            const uint32_t kb = (uint32_t)ks * 32;   // 16 halves = 32 B
            uint32_t ah[4][4], al[4][4], bh[NP][4], bl[NP][4];
            #pragma unroll
            for (int mt = 0; mt < 4; ++mt) {
                const uint32_t ro = (uint32_t)(wm * 64 + mt * 16) * (RS * 2);
                ldm_x4(ah[mt], sAh + ro + kb + aoff);
                ldm_x4(al[mt], sAl + ro + kb + aoff);
            }
            #pragma unroll
            for (int p = 0; p < NP; ++p) {
                const uint32_t no = (uint32_t)(wn * NT * 8 + p * 16) * (RS * 2);
                ldm_x4(bh[p], sBh + no + kb + boff);
                ldm_x4(bl[p], sBl + no + kb + boff);
            }
            #pragma unroll
            for (int mt = 0; mt < 4; ++mt)
                #pragma unroll
                for (int p = 0; p < NP; ++p) {
                    mma_f16(acc[mt][2*p],   ah[mt], &bh[p][0]);
                    mma_f16(acc[mt][2*p+1], ah[mt], &bh[p][2]);
                    mma_f16(acc[mt][2*p],   ah[mt], &bl[p][0]);
                    mma_f16(acc[mt][2*p+1], ah[mt], &bl[p][2]);
                    mma_f16(acc[mt][2*p],   al[mt], &bh[p][0]);
                    mma_f16(acc[mt][2*p+1], al[mt], &bh[p][2]);
                }
        }
        __syncthreads();
    }

    // ---------------- epilogue: bias + act + store ----------------
    #pragma unroll
    for (int mt = 0; mt < 4; ++mt) {
        const int row = m0 + wm * 64 + mt * 16 + g;
        #pragma unroll
        for (int nt = 0; nt < NT; ++nt) {
            const int col = n0 + wn * (NT * 8) + nt * 8 + tig * 2;
            const float b0 = bias[col], b1 = bias[col + 1];
            float v0 = acc[mt][nt][0] + b0;
            float v1 = acc[mt][nt][1] + b1;
            float v2 = acc[mt][nt][2] + b0;
            float v3 = acc[mt][nt][3] + b1;
            if (ACT == 1) {
                v0 = fmaxf(v0, 0.0f); v1 = fmaxf(v1, 0.0f);
                v2 = fmaxf(v2, 0.0f); v3 = fmaxf(v3, 0.0f);
            } else if (ACT == 2) {
                v0 = 1.0f / (1.0f + expf(-v0)); v1 = 1.0f / (1.0f + expf(-v1));
                v2 = 1.0f / (1.0f + expf(-v2)); v3 = 1.0f / (1.0f + expf(-v3));
            }
            *reinterpret_cast<float2*>(C + (size_t)row * Ntot + col) = make_float2(v0, v1);
            *reinterpret_cast<float2*>(C + (size_t)(row + 8) * Ntot + col) = make_float2(v2, v3);
        }
    }
}

// ---------------- per-bag finish (unchanged, passed R2/R4) ----------------
__global__ void __launch_bounds__(128)
finish_kernel(const float* __restrict__ d2v, const float* __restrict__ D3,
              const float* __restrict__ db3, const float* __restrict__ m,
              const float* __restrict__ u,   const float* __restrict__ H3,
              const float* __restrict__ E,   const float* __restrict__ eb,
              float* __restrict__ outw, float* __restrict__ outv)
{
    const int n   = blockIdx.x;
    const int tid = threadIdx.x;

    __shared__ float s_d2[CC][DET2 + 1];
    __shared__ float s_D3[DET2];
    __shared__ float s_z[CC];
    __shared__ float s_w2[CC];
    __shared__ float s_w[CC];
    __shared__ int   s_keep[CC];
    __shared__ float s_red[128];
    __shared__ float s_mx, s_sum;

    const float* d2b = d2v + (size_t)n * CC * DET2;
    for (int idx = tid; idx < CC * DET2; idx += 128)
        s_d2[idx >> 6][idx & 63] = d2b[idx];
    if (tid < DET2) s_D3[tid] = D3[tid];
    __syncthreads();

    if (tid < CC) {
        const int c = tid;
        float dd = db3[0];
        #pragma unroll
        for (int j = 0; j < DET2; j++) dd = fmaf(s_d2[c][j], s_D3[j], dd);
        float logit = m[(size_t)n * CC + c] * dd;
        float uu = u[(size_t)n * CC + c];
        float gn = -logf(-logf(uu));
        s_z[c] = (logit + gn) / TAU;
    }
    __syncthreads();

    if (tid == 0) {
        float mx = s_z[0];
        for (int c = 1; c < CC; c++) mx = fmaxf(mx, s_z[c]);
        s_mx = mx;
    }
    __syncthreads();
    if (tid < CC) s_w2[tid] = expf(s_z[tid] - s_mx);
    __syncthreads();
    if (tid == 0) {
        float s = 0.0f;
        for (int c = 0; c < CC; c++) s += s_w2[c];
        s_sum = s;
    }
    __syncthreads();
    if (tid < CC) s_w2[tid] = s_w2[tid] / s_sum;
    __syncthreads();

    if (tid < CC) {
        const int c = tid;
        const float v = s_w2[c];
        int rank = 0;
        for (int c2 = 0; c2 < CC; c2++) {
            float v2 = s_w2[c2];
            rank += (v2 < v) || (v2 == v && c2 < c);
        }
        s_keep[c] = (rank >= KDROP);
    }
    __syncthreads();

    if (tid == 0) {
        float mx = -INFINITY;
        for (int c = 0; c < CC; c++)
            if (s_keep[c]) mx = fmaxf(mx, s_w2[c]);
        s_mx = mx;
    }
    __syncthreads();
    if (tid < CC) s_red[tid] = s_keep[tid] ? expf(s_w2[tid] - s_mx) : 0.0f;
    __syncthreads();
    if (tid == 0) {
        float s = 0.0f;
        for (int c = 0; c < CC; c++) s += s_red[c];
        s_sum = s;
    }
    __syncthreads();
    if (tid < CC) {
        float wv = s_keep[tid] ? s_red[tid] / s_sum : 0.0f;
        s_w[tid] = wv;
        outw[(size_t)n * CC + tid] = wv;
    }
    __syncthreads();

    {
        const float* h3b = H3 + (size_t)n * CC * HD3;
        float a = 0.0f;
        #pragma unroll 8
        for (int c = 0; c < CC; c++)
            a = fmaf(s_w[c], h3b[(size_t)c * HD3 + tid], a);
        s_red[tid] = a * E[tid];
    }
    __syncthreads();
    for (int off = 64; off > 0; off >>= 1) {
        if (tid < off) s_red[tid] += s_red[tid + off];
        __syncthreads();
    }
    if (tid == 0) outv[n] = s_red[0] + eb[0];
}

// ---------------- launch ----------------
static inline int smem_bytes_for(int BN) {
    return 2 * (2 * 128 * RS * 2 + 2 * BN * RS * 2);
}

extern "C" void kernel_launch(void* const* d_in, const int* in_sizes, int n_in,
                              void* d_out, int out_size)
{
    const float* x   = (const float*)d_in[0];
    const float* m   = (const float*)d_in[1];
    const float* u   = (const float*)d_in[2];
    const float* W1  = (const float*)d_in[3];
    const float* b1  = (const float*)d_in[4];
    const float* W2  = (const float*)d_in[5];
    const float* b2  = (const float*)d_in[6];
    const float* W3  = (const float*)d_in[7];
    const float* b3  = (const float*)d_in[8];
    const float* D1  = (const float*)d_in[9];
    const float* db1 = (const float*)d_in[10];
    const float* D2  = (const float*)d_in[11];
    const float* db2 = (const float*)d_in[12];
    const float* D3  = (const float*)d_in[13];
    const float* db3 = (const float*)d_in[14];
    const float* E   = (const float*)d_in[15];
    const float* eb  = (const float*)d_in[16];

    static float *pH = nullptr, *pH2, *pH3, *pd1, *pd2, *pscr;
    static __half *pwh, *pwl;
    if (!pH) {
        cudaGetSymbolAddress((void**)&pH,   g_H);
        cudaGetSymbolAddress((void**)&pH2,  g_H2);
        cudaGetSymbolAddress((void**)&pH3,  g_H3);
        cudaGetSymbolAddress((void**)&pd1,  g_d1);
        cudaGetSymbolAddress((void**)&pd2,  g_d2);
        cudaGetSymbolAddress((void**)&pscr, g_scr);
        cudaGetSymbolAddress((void**)&pwh,  g_wh);
        cudaGetSymbolAddress((void**)&pwl,  g_wl);
        cudaFuncSetAttribute(mma_gemm_h<128,1>, cudaFuncAttributeMaxDynamicSharedMemorySize, smem_bytes_for(128));
        cudaFuncSetAttribute(mma_gemm_h<128,2>, cudaFuncAttributeMaxDynamicSharedMemorySize, smem_bytes_for(128));
        cudaFuncSetAttribute(mma_gemm_h<64,2>,  cudaFuncAttributeMaxDynamicSharedMemorySize, smem_bytes_for(64));
    }

    float* outw = (float*)d_out;
    float* outv;
    if (out_size >= MROWS + NB)      { outv = outw + MROWS; }
    else if (out_size == MROWS)      { outv = pscr; }
    else                             { outv = (float*)d_out; outw = pscr; }

    // weight prep: transpose + fp16 hi/lo decompose
    prep_weights<<<(IND*HD1 + 255)/256, 256>>>(W1, pwh + OFF_W1, pwl + OFF_W1, IND,  HD1);
    prep_weights<<<(HD1*HD2 + 255)/256, 256>>>(W2, pwh + OFF_W2, pwl + OFF_W2, HD1,  HD2);
    prep_weights<<<(HD2*HD3 + 255)/256, 256>>>(W3, pwh + OFF_W3, pwl + OFF_W3, HD2,  HD3);
    prep_weights<<<(HD3*DET1 + 255)/256, 256>>>(D1, pwh + OFF_D1, pwl + OFF_D1, HD3,  DET1);
    prep_weights<<<(DET1*DET2 + 255)/256, 256>>>(D2, pwh + OFF_D2, pwl + OFF_D2, DET1, DET2);

    const int gy = MROWS / 128;   // 1024
    mma_gemm_h<128,1><<<dim3(2, gy), 128, smem_bytes_for(128)>>>(
        x,   pwh + OFF_W1, pwl + OFF_W1, b1,  pH,  IND,  HD1);
    mma_gemm_h<128,1><<<dim3(2, gy), 128, smem_bytes_for(128)>>>(
        pH,  pwh + OFF_W2, pwl + OFF_W2, b2,  pH2, HD1,  HD2);
    mma_gemm_h<128,1><<<dim3(1, gy), 128, smem_bytes_for(128)>>>(
        pH2, pwh + OFF_W3, pwl + OFF_W3, b3,  pH3, HD2,  HD3);
    mma_gemm_h<128,2><<<dim3(1, gy), 128, smem_bytes_for(128)>>>(
        pH3, pwh + OFF_D1, pwl + OFF_D1, db1, pd1, HD3,  DET1);
    mma_gemm_h<64,2><<<dim3(1, gy), 128, smem_bytes_for(64)>>>(
        pd1, pwh + OFF_D2, pwl + OFF_D2, db2, pd2, DET1, DET2);

    finish_kernel<<<NB, 128>>>(pd2, D3, db3, m, u, pH3, E, eb, outw, outv);
}